// round 3
// baseline (speedup 1.0000x reference)
#include <cuda_runtime.h>

#define N_PTS 4096
#define TPB   256
#define BLOCKS_PER_PAIR (N_PTS / TPB)   // 16
#define T_DIM 4
#define INV_SCALE (1.0f / (T_DIM * N_PTS))

__global__ void hd_init_out(float* out) {
    if (threadIdx.x < 2) out[threadIdx.x] = 0.0f;
}

__global__ __launch_bounds__(TPB)
void hd_nn_kernel(const float* __restrict__ d1,
                  const float* __restrict__ d2,
                  float* __restrict__ out) {
    __shared__ float4 s2[N_PTS];            // (bx, by, bz, |b|^2)  -> 64 KB
    __shared__ float red[TPB / 32];

    const int pair = blockIdx.y;            // 0..7 : pair = b*4 + t
    const float* p2 = d2 + (size_t)pair * N_PTS * 3;

    // Stage set-2 points + squared norms into shared memory
    for (int j = threadIdx.x; j < N_PTS; j += TPB) {
        float bx = p2[3 * j + 0];
        float by = p2[3 * j + 1];
        float bz = p2[3 * j + 2];
        float nb2 = fmaf(bx, bx, fmaf(by, by, bz * bz));
        s2[j] = make_float4(bx, by, bz, nb2);
    }
    __syncthreads();

    // This thread's set-1 point
    const int i = blockIdx.x * TPB + threadIdx.x;
    const float* p1 = d1 + (size_t)pair * N_PTS * 3 + 3 * i;
    const float ax = p1[0], ay = p1[1], az = p1[2];
    const float na2 = fmaf(ax, ax, fmaf(ay, ay, az * az));
    const float axn = -2.0f * ax;
    const float ayn = -2.0f * ay;
    const float azn = -2.0f * az;

    // min_j (|b_j|^2 - 2 a.b_j)   [add |a|^2 after the loop]
    float m0 = 3.0e38f, m1 = 3.0e38f, m2 = 3.0e38f, m3 = 3.0e38f;

    #pragma unroll 4
    for (int j = 0; j < N_PTS; j += 4) {
        float4 q0 = s2[j + 0];
        float4 q1 = s2[j + 1];
        float4 q2 = s2[j + 2];
        float4 q3 = s2[j + 3];

        float t0 = fmaf(axn, q0.x, q0.w);
        float t1 = fmaf(axn, q1.x, q1.w);
        float t2 = fmaf(axn, q2.x, q2.w);
        float t3 = fmaf(axn, q3.x, q3.w);
        t0 = fmaf(ayn, q0.y, t0);
        t1 = fmaf(ayn, q1.y, t1);
        t2 = fmaf(ayn, q2.y, t2);
        t3 = fmaf(ayn, q3.y, t3);
        t0 = fmaf(azn, q0.z, t0);
        t1 = fmaf(azn, q1.z, t1);
        t2 = fmaf(azn, q2.z, t2);
        t3 = fmaf(azn, q3.z, t3);
        m0 = fminf(m0, t0);
        m1 = fminf(m1, t1);
        m2 = fminf(m2, t2);
        m3 = fminf(m3, t3);
    }

    float m = fminf(fminf(m0, m1), fminf(m2, m3));
    float d = sqrtf(fmaxf(na2 + m, 0.0f));

    // Block-reduce sum of d
    #pragma unroll
    for (int off = 16; off > 0; off >>= 1)
        d += __shfl_xor_sync(0xFFFFFFFFu, d, off);

    const int lane = threadIdx.x & 31;
    const int wid  = threadIdx.x >> 5;
    if (lane == 0) red[wid] = d;
    __syncthreads();

    if (wid == 0) {
        float v = (lane < TPB / 32) ? red[lane] : 0.0f;
        #pragma unroll
        for (int off = 4; off > 0; off >>= 1)
            v += __shfl_xor_sync(0xFFFFFFFFu, v, off);
        if (lane == 0)
            atomicAdd(&out[pair >> 2], v * INV_SCALE);
    }
}

extern "C" void kernel_launch(void* const* d_in, const int* in_sizes, int n_in,
                              void* d_out, int out_size) {
    const float* d1 = (const float*)d_in[0];
    const float* d2 = (const float*)d_in[1];
    float* out = (float*)d_out;

    hd_init_out<<<1, 32>>>(out);
    dim3 grid(BLOCKS_PER_PAIR, 8);
    hd_nn_kernel<<<grid, TPB>>>(d1, d2, out);
}

// round 6
// speedup vs baseline: 2.1514x; 2.1514x over previous
#include <cuda_runtime.h>

#define N_PTS   4096
#define PAIRS   8
#define TPB     256
#define J_TILE  512
#define I_TILE  512                       // 2 i-points per thread
#define J_SPLITS (N_PTS / J_TILE)         // 8
#define I_GROUPS (N_PTS / I_TILE)         // 8
#define T_DIM   4
#define INV_SCALE (1.0f / (T_DIM * N_PTS))
#define FINF    3.0e38f

// Per-(pair,i) running min of (|b|^2 - 2 a.b), stored as order-preserving uint keys
__device__ unsigned int g_minkey[PAIRS * N_PTS];

__device__ __forceinline__ unsigned int enc_f(float f) {
    unsigned int b = __float_as_uint(f);
    return (b & 0x80000000u) ? ~b : (b | 0x80000000u);
}
__device__ __forceinline__ float dec_f(unsigned int k) {
    return (k & 0x80000000u) ? __uint_as_float(k ^ 0x80000000u)
                             : __uint_as_float(~k);
}

__global__ void hd_init(float* out) {
    int idx = blockIdx.x * blockDim.x + threadIdx.x;
    if (idx < PAIRS * N_PTS) g_minkey[idx] = 0xFF800000u;   // enc(+inf)
    if (idx < 2) out[idx] = 0.0f;
}

__global__ __launch_bounds__(TPB)
void hd_nn_kernel(const float* __restrict__ d1,
                  const float* __restrict__ d2) {
    __shared__ float4 s2[J_TILE];                           // 8 KB

    const int pair  = blockIdx.z;
    const int ibase = blockIdx.y * I_TILE;
    const int jbase = blockIdx.x * J_TILE;

    // Stage this block's j-chunk of set-2 (+ squared norms)
    const float* p2 = d2 + ((size_t)pair * N_PTS + jbase) * 3;
    #pragma unroll
    for (int j = threadIdx.x; j < J_TILE; j += TPB) {
        float bx = p2[3 * j + 0];
        float by = p2[3 * j + 1];
        float bz = p2[3 * j + 2];
        s2[j] = make_float4(bx, by, bz, fmaf(bx, bx, fmaf(by, by, bz * bz)));
    }
    __syncthreads();

    // Two set-1 points per thread
    const int i0 = ibase + threadIdx.x;
    const int i1 = i0 + TPB;
    const float* pa0 = d1 + ((size_t)pair * N_PTS + i0) * 3;
    const float* pa1 = d1 + ((size_t)pair * N_PTS + i1) * 3;
    const float ax0 = -2.0f * pa0[0], ay0 = -2.0f * pa0[1], az0 = -2.0f * pa0[2];
    const float ax1 = -2.0f * pa1[0], ay1 = -2.0f * pa1[1], az1 = -2.0f * pa1[2];

    float m00 = FINF, m01 = FINF;   // point i0, two interleaved chains
    float m10 = FINF, m11 = FINF;   // point i1

    #pragma unroll 4
    for (int j = 0; j < J_TILE; j += 2) {
        float4 q0 = s2[j + 0];
        float4 q1 = s2[j + 1];

        float t00 = fmaf(ax0, q0.x, q0.w);
        float t01 = fmaf(ax0, q1.x, q1.w);
        float t10 = fmaf(ax1, q0.x, q0.w);
        float t11 = fmaf(ax1, q1.x, q1.w);
        t00 = fmaf(ay0, q0.y, t00);
        t01 = fmaf(ay0, q1.y, t01);
        t10 = fmaf(ay1, q0.y, t10);
        t11 = fmaf(ay1, q1.y, t11);
        t00 = fmaf(az0, q0.z, t00);
        t01 = fmaf(az0, q1.z, t01);
        t10 = fmaf(az1, q0.z, t10);
        t11 = fmaf(az1, q1.z, t11);
        m00 = fminf(m00, t00);
        m01 = fminf(m01, t01);
        m10 = fminf(m10, t10);
        m11 = fminf(m11, t11);
    }

    unsigned int* base = g_minkey + (size_t)pair * N_PTS;
    atomicMin(base + i0, enc_f(fminf(m00, m01)));
    atomicMin(base + i1, enc_f(fminf(m10, m11)));
}

__global__ __launch_bounds__(TPB)
void hd_final(const float* __restrict__ d1, float* __restrict__ out) {
    __shared__ float red[TPB / 32];
    const int pair = blockIdx.x;
    const unsigned int* base = g_minkey + (size_t)pair * N_PTS;

    float acc = 0.0f;
    for (int i = threadIdx.x; i < N_PTS; i += TPB) {
        float m = dec_f(base[i]);
        const float* pa = d1 + ((size_t)pair * N_PTS + i) * 3;
        float na2 = fmaf(pa[0], pa[0], fmaf(pa[1], pa[1], pa[2] * pa[2]));
        acc += sqrtf(fmaxf(na2 + m, 0.0f));
    }

    #pragma unroll
    for (int off = 16; off > 0; off >>= 1)
        acc += __shfl_xor_sync(0xFFFFFFFFu, acc, off);

    const int lane = threadIdx.x & 31;
    const int wid  = threadIdx.x >> 5;
    if (lane == 0) red[wid] = acc;
    __syncthreads();

    if (wid == 0) {
        float v = (lane < TPB / 32) ? red[lane] : 0.0f;
        #pragma unroll
        for (int off = 4; off > 0; off >>= 1)
            v += __shfl_xor_sync(0xFFFFFFFFu, v, off);
        if (lane == 0)
            atomicAdd(&out[pair >> 2], v * INV_SCALE);
    }
}

extern "C" void kernel_launch(void* const* d_in, const int* in_sizes, int n_in,
                              void* d_out, int out_size) {
    const float* d1 = (const float*)d_in[0];
    const float* d2 = (const float*)d_in[1];
    float* out = (float*)d_out;

    hd_init<<<(PAIRS * N_PTS + TPB - 1) / TPB, TPB>>>(out);
    dim3 grid(J_SPLITS, I_GROUPS, PAIRS);
    hd_nn_kernel<<<grid, TPB>>>(d1, d2);
    hd_final<<<PAIRS, TPB>>>(d1, out);
}